// round 7
// baseline (speedup 1.0000x reference)
#include <cuda_runtime.h>
#include <math.h>
#include <limits.h>

#define BATCH 4096
#define DIM   512
#define NCLS  128
#define BPC   4                  // blocks per class
#define NBLK  (NCLS * BPC)       // 512
#define CH    16                 // smem chunk rows
#define MAXM  1024               // member list cap

__device__ double g_partial[NBLK];
__device__ int    g_pcount[NBLK];
__device__ int    g_done;        // zero-init; last block resets to 0 each run

__global__ void __launch_bounds__(256, 2) k_class(
    const float* __restrict__ batch,
    const int*   __restrict__ labels,
    const int*   __restrict__ anchors,
    const int*   __restrict__ negatives,
    float*       __restrict__ out)
{
    const int c    = blockIdx.x >> 2;
    const int quad = blockIdx.x & 3;
    const int tid  = threadIdx.x;
    const int lane = tid & 31;
    const int wid  = tid >> 5;             // 0..7
    const int slot = quad * 8 + wid;       // 0..31 anchor slot across the class's 4 blocks

    __shared__ __align__(16) float  sh_rows[CH][DIM];
    __shared__ int    sh_raw[MAXM];
    __shared__ int    sh_memb[MAXM];       // sorted: identical in all 4 blocks of this class
    __shared__ double sh_wsum[8];
    __shared__ int    sh_wcnt[8];
    __shared__ int    sh_cnt;
    __shared__ int    sh_last;

    // ---- build member list (atomic order nondeterministic) ----
    if (tid == 0) sh_cnt = 0;
    __syncthreads();
    for (int s = tid; s < BATCH; s += 256) {
        if (labels[s] == c) {
            int pos = atomicAdd(&sh_cnt, 1);
            if (pos < MAXM) sh_raw[pos] = s;
        }
    }
    __syncthreads();
    const int cnt = min(sh_cnt, MAXM);

    // ---- rank-sort ascending: deterministic shared view across the 4 blocks ----
    for (int t = tid; t < cnt; t += 256) {
        int v = sh_raw[t];
        int rank = 0;
        for (int k = 0; k < cnt; ++k) rank += (sh_raw[k] < v);
        sh_memb[rank] = v;
    }
    __syncthreads();

    double wsum = 0.0;
    int    wcnt = 0;

    if (cnt >= 3) {   // valid iff (cnt-1) > 1
        const int npass  = (cnt + 31) >> 5;          // one anchor per warp-slot per pass
        const int nchunk = (cnt + CH - 1) / CH;

        for (int pass = 0; pass < npass; ++pass) {
            const int  m     = slot + 32 * pass;
            const bool valid = (m < cnt);
            const int  aidx_m = valid ? sh_memb[m] : 0;

            float areg[16];
            if (valid) {
                const float* ap = batch + (size_t)aidx_m * DIM;
                #pragma unroll
                for (int k = 0; k < 16; ++k) areg[k] = ap[lane + 32 * k];
            }
            float bestd = INFINITY;
            int   bestj = INT_MAX;

            for (int chb = 0; chb < nchunk; ++chb) {
                const int base = chb * CH;
                const int nrow = min(CH, cnt - base);
                __syncthreads();
                {   // cooperative chunk load: 16 threads per row, float4
                    int row = tid >> 4, sub = tid & 15;
                    if (row < nrow) {
                        const float4* src = (const float4*)(batch + (size_t)sh_memb[base + row] * DIM);
                        float4*       dst = (float4*)&sh_rows[row][0];
                        #pragma unroll
                        for (int k = 0; k < 8; ++k) dst[sub + 16 * k] = src[sub + 16 * k];
                    }
                }
                __syncthreads();

                if (valid) {
                    for (int q = 0; q < nrow; ++q) {
                        const int j = sh_memb[base + q];
                        if (j == aidx_m) continue;
                        float acc = 0.f;
                        #pragma unroll
                        for (int k = 0; k < 16; ++k) {
                            float d = areg[k] - sh_rows[q][lane + 32 * k];
                            acc = fmaf(d, d, acc);
                        }
                        #pragma unroll
                        for (int o = 16; o; o >>= 1) acc += __shfl_xor_sync(0xFFFFFFFFu, acc, o);
                        if (acc < bestd || (acc == bestd && j < bestj)) { bestd = acc; bestj = j; }
                    }
                }
            }

            // ---- epilogue for this pass's anchor ----
            if (valid) {
                const int t_   = aidx_m;
                const int a    = anchors[t_];
                const int nidx = negatives[t_];
                float d_ap, d_an;
                if (a == t_) {  // anchor row == mining row: bestd is d_ap^2 exactly (_pair_dist)
                    d_ap = sqrtf(fmaxf(bestd, 1e-12f));
                    const float* nr_ = batch + (size_t)nidx * DIM;
                    float acc = 0.f;
                    #pragma unroll
                    for (int k = 0; k < 16; ++k) {
                        float d = areg[k] - nr_[lane + 32 * k];
                        acc = fmaf(d, d, acc);
                    }
                    #pragma unroll
                    for (int o = 16; o; o >>= 1) acc += __shfl_xor_sync(0xFFFFFFFFu, acc, o);
                    d_an = sqrtf(fmaxf(acc, 1e-12f));
                } else {        // general path (kept for correctness)
                    const int p = bestj;
                    const float* ar_ = batch + (size_t)a * DIM;
                    const float* pr_ = batch + (size_t)p * DIM;
                    const float* nr_ = batch + (size_t)nidx * DIM;
                    float acc1 = 0.f, acc2 = 0.f;
                    #pragma unroll
                    for (int k = 0; k < 16; ++k) {
                        float va = ar_[lane + 32 * k];
                        float d1 = va - pr_[lane + 32 * k];
                        float d2 = va - nr_[lane + 32 * k];
                        acc1 = fmaf(d1, d1, acc1); acc2 = fmaf(d2, d2, acc2);
                    }
                    #pragma unroll
                    for (int o = 16; o; o >>= 1) {
                        acc1 += __shfl_xor_sync(0xFFFFFFFFu, acc1, o);
                        acc2 += __shfl_xor_sync(0xFFFFFFFFu, acc2, o);
                    }
                    d_ap = sqrtf(fmaxf(acc1, 1e-12f));
                    d_an = sqrtf(fmaxf(acc2, 1e-12f));
                }
                if (lane == 0) {
                    // (s_an - s_ap)/TEMP = (d_ap - d_an)/(2*0.05)
                    float x   = (d_ap - d_an) * 10.f;
                    float per = fmaxf(x, 0.f) + log1pf(expf(-fabsf(x)));
                    wsum += (double)per; wcnt += 1;
                }
            }
        }
    }

    if (lane == 0) { sh_wsum[wid] = wsum; sh_wcnt[wid] = wcnt; }
    __syncthreads();
    if (tid == 0) {
        double s = 0.0; int n = 0;
        #pragma unroll
        for (int w = 0; w < 8; ++w) { s += sh_wsum[w]; n += sh_wcnt[w]; }
        g_partial[blockIdx.x] = s;
        g_pcount[blockIdx.x]  = n;
        __threadfence();
        int old = atomicAdd(&g_done, 1);
        sh_last = (old == NBLK - 1);
    }
    __syncthreads();

    // ---- last block reduces all partials (no second launch) ----
    if (sh_last) {
        double s = 0.0; int n = 0;
        for (int t2 = tid; t2 < NBLK; t2 += 256) { s += g_partial[t2]; n += g_pcount[t2]; }
        #pragma unroll
        for (int o = 16; o; o >>= 1) {
            s += __shfl_xor_sync(0xFFFFFFFFu, s, o);
            n += __shfl_xor_sync(0xFFFFFFFFu, n, o);
        }
        if (lane == 0) { sh_wsum[wid] = s; sh_wcnt[wid] = n; }
        __syncthreads();
        if (tid == 0) {
            double ts = 0.0; int tn = 0;
            #pragma unroll
            for (int w = 0; w < 8; ++w) { ts += sh_wsum[w]; tn += sh_wcnt[w]; }
            out[0] = (float)(ts / (double)tn);
            g_done = 0;   // reset for next graph replay
        }
    }
}

extern "C" void kernel_launch(void* const* d_in, const int* in_sizes, int n_in,
                              void* d_out, int out_size) {
    const float* batch     = (const float*)d_in[0];
    const int*   labels    = (const int*)d_in[1];
    const int*   anchors   = (const int*)d_in[2];
    const int*   negatives = (const int*)d_in[3];
    float* out = (float*)d_out;

    k_class<<<NBLK, 256>>>(batch, labels, anchors, negatives, out);
}